// round 4
// baseline (speedup 1.0000x reference)
#include <cuda_runtime.h>

// Problem constants (fixed shapes per reference)
#define NVERT   1000000
#define NEDGE   3000000
#define IMG_W   1024
#define IMG_HW  (1024*1024)
#define MAXD    10.0f
#define CREGU_D 2000.0

// ---- device scratch (no allocation allowed) ----
__device__ float4       g_dv[NVERT];     // vertices - vertices_ref  (w unused/0)
__device__ float4       g_acc[NVERT];    // xyz = neigh segment sum, w = deg
__device__ unsigned int g_depth[IMG_HW]; // float bits, atomicMin (all positive)
__device__ double       g_vsum[3];       // vertex coordinate sums
__device__ double       g_energy[2];     // [0] = e_data, [1] = sum(ldv^2)
__device__ float        g_xf[24];        // M[9], b[3], A[9], c[3]
__device__ int          g_edges64;       // 1 if edges buffer is int64 pairs

// ---------------------------------------------------------------------------
// block-level fp32 sum (256 threads); caller provides 32-float shared buffer
__device__ __forceinline__ float block_sum(float v, float* sh) {
    #pragma unroll
    for (int o = 16; o; o >>= 1) v += __shfl_down_sync(0xffffffffu, v, o);
    int lane = threadIdx.x & 31, w = threadIdx.x >> 5;
    __syncthreads();                       // protect shared reuse across calls
    if (lane == 0) sh[w] = v;
    __syncthreads();
    int nw = blockDim.x >> 5;
    v = (threadIdx.x < (unsigned)nw) ? sh[threadIdx.x] : 0.0f;
    if (w == 0) {
        #pragma unroll
        for (int o = 16; o; o >>= 1) v += __shfl_down_sync(0xffffffffu, v, o);
    }
    return v;
}

// ---------------------------------------------------------------------------
__global__ void k_init() {
    int i = blockIdx.x * blockDim.x + threadIdx.x;
    int stride = gridDim.x * blockDim.x;
    for (int j = i; j < IMG_HW; j += stride) g_depth[j] = 0x41200000u; // 10.0f
    for (int j = i; j < NVERT;  j += stride) g_acc[j] = make_float4(0.f,0.f,0.f,0.f);
    if (i == 0) {
        g_vsum[0] = g_vsum[1] = g_vsum[2] = 0.0;
        g_energy[0] = g_energy[1] = 0.0;
    }
}

// Detect edges dtype: int64 layout => odd 32-bit words are zero high-halves.
__global__ void k_detect(const int* __restrict__ e) {
    __shared__ int any;
    if (threadIdx.x == 0) any = 0;
    __syncthreads();
    if (e[2 * threadIdx.x + 1] != 0) atomicOr(&any, 1);
    __syncthreads();
    if (threadIdx.x == 0) g_edges64 = (any == 0) ? 1 : 0;
}

// per-vertex: dv = v - vref (padded float4 for aligned random gather later),
// and reduce sum of vertex coords for the mean.
__global__ void k_prep(const float* __restrict__ v, const float* __restrict__ vr) {
    __shared__ float sh[32];
    int i = blockIdx.x * blockDim.x + threadIdx.x;
    float sx = 0.f, sy = 0.f, sz = 0.f;
    if (i < NVERT) {
        float x = v[3*i], y = v[3*i+1], z = v[3*i+2];
        g_dv[i] = make_float4(x - vr[3*i], y - vr[3*i+1], z - vr[3*i+2], 0.f);
        sx = x; sy = y; sz = z;
    }
    float bx = block_sum(sx, sh);
    float by = block_sum(sy, sh);
    float bz = block_sum(sz, sh);
    if (threadIdx.x == 0) {
        atomicAdd(&g_vsum[0], (double)bx);
        atomicAdd(&g_vsum[1], (double)by);
        atomicAdd(&g_vsum[2], (double)bz);
    }
}

// single-thread: fold mean/quaternion/extrinsic/intrinsic into affine maps
//   p_cam = M*v + b ;  proj = A*v + c  (A row2 == M row2, so z divisor = p_cam.z)
__global__ void k_setup(const float* __restrict__ q, const float* __restrict__ t,
                        const float* __restrict__ K, const float* __restrict__ E) {
    double inv = 1.0 / (double)NVERT;
    double mx = g_vsum[0] * inv, my = g_vsum[1] * inv, mz = g_vsum[2] * inv;
    double qx = q[0], qy = q[1], qz = q[2], qw = q[3];
    double n = 1.0 / sqrt(qx*qx + qy*qy + qz*qz + qw*qw);
    qx *= n; qy *= n; qz *= n; qw *= n;
    double R[9];
    R[0] = 1.0 - 2.0*(qy*qy + qz*qz); R[1] = 2.0*(qx*qy - qw*qz); R[2] = 2.0*(qx*qz + qw*qy);
    R[3] = 2.0*(qx*qy + qw*qz); R[4] = 1.0 - 2.0*(qx*qx + qz*qz); R[5] = 2.0*(qy*qz - qw*qx);
    R[6] = 2.0*(qx*qz - qw*qy); R[7] = 2.0*(qy*qz + qw*qx); R[8] = 1.0 - 2.0*(qx*qx + qy*qy);
    double M[9], b[3];
    for (int r = 0; r < 3; r++) {
        for (int c = 0; c < 3; c++)
            M[r*3+c] = (double)E[r*4+0]*R[0*3+c] + (double)E[r*4+1]*R[1*3+c] + (double)E[r*4+2]*R[2*3+c];
        b[r] = (double)E[r*4+0]*t[0] + (double)E[r*4+1]*t[1] + (double)E[r*4+2]*t[2] + (double)E[r*4+3]
             - (M[r*3+0]*mx + M[r*3+1]*my + M[r*3+2]*mz);
    }
    double A[9], c[3];
    for (int r = 0; r < 3; r++) {
        for (int cc = 0; cc < 3; cc++)
            A[r*3+cc] = (double)K[r*3+0]*M[0*3+cc] + (double)K[r*3+1]*M[1*3+cc] + (double)K[r*3+2]*M[2*3+cc];
        c[r] = (double)K[r*3+0]*b[0] + (double)K[r*3+1]*b[1] + (double)K[r*3+2]*b[2];
    }
    for (int j = 0; j < 9; j++) { g_xf[j] = (float)M[j]; g_xf[12+j] = (float)A[j]; }
    for (int j = 0; j < 3; j++) { g_xf[9+j] = (float)b[j]; g_xf[21+j] = (float)c[j]; }
}

// per-vertex projection + z-buffer scatter (atomicMin on positive-float bits)
__global__ void k_project(const float* __restrict__ v) {
    __shared__ float xf[24];
    if (threadIdx.x < 24) xf[threadIdx.x] = g_xf[threadIdx.x];
    __syncthreads();
    int i = blockIdx.x * blockDim.x + threadIdx.x;
    if (i >= NVERT) return;
    float x = v[3*i], y = v[3*i+1], z = v[3*i+2];
    float pz = fmaf(xf[6], x, fmaf(xf[7], y, fmaf(xf[8], z, xf[11])));
    float px = fmaf(xf[12], x, fmaf(xf[13], y, fmaf(xf[14], z, xf[21])));
    float py = fmaf(xf[15], x, fmaf(xf[16], y, fmaf(xf[17], z, xf[22])));
    float u  = px / pz;
    float vv = py / pz;
    float xi = fminf(fmaxf(rintf(u),  0.0f), (float)(IMG_W - 1));
    float yi = fminf(fmaxf(rintf(vv), 0.0f), (float)(IMG_W - 1));
    int flat = (int)yi * IMG_W + (int)xi;
    float zv = (pz > 0.0f) ? pz : MAXD;
    atomicMin(&g_depth[flat], __float_as_uint(zv));
}

// per-edge scatter: neigh[src] += dv[dst], deg[src] += 1 (packed in .w)
// Handles both int32-pair and int64-pair edge layouts (uniform branch).
__global__ void k_edges(const void* __restrict__ ep) {
    int i = blockIdx.x * blockDim.x + threadIdx.x;
    if (i >= NEDGE) return;
    int s, d;
    if (g_edges64) {
        const longlong2* e = (const longlong2*)ep;
        longlong2 p = e[i];
        s = (int)p.x; d = (int)p.y;
    } else {
        const int2* e = (const int2*)ep;
        int2 p = e[i];
        s = p.x; d = p.y;
    }
    float4 dv = g_dv[d];
    float* a = (float*)&g_acc[s];
    atomicAdd(a + 0, dv.x);
    atomicAdd(a + 1, dv.y);
    atomicAdd(a + 2, dv.z);
    atomicAdd(a + 3, 1.0f);
}

// depth-vs-hand image energy: sum((depth - hand)^2), 4 px/thread
__global__ void k_edata(const float* __restrict__ hand) {
    __shared__ float sh[32];
    int i = blockIdx.x * blockDim.x + threadIdx.x;
    float s = 0.f;
    if (i < IMG_HW / 4) {
        uint4  db = ((const uint4*)g_depth)[i];
        float4 hb = ((const float4*)hand)[i];
        float d0 = __uint_as_float(db.x) - hb.x;
        float d1 = __uint_as_float(db.y) - hb.y;
        float d2 = __uint_as_float(db.z) - hb.z;
        float d3 = __uint_as_float(db.w) - hb.w;
        s = d0*d0 + d1*d1 + d2*d2 + d3*d3;
    }
    float bs = block_sum(s, sh);
    if (threadIdx.x == 0) atomicAdd(&g_energy[0], (double)bs);
}

// rigid energy: sum over vertices of ||deg*dv - neigh||^2
__global__ void k_erigid() {
    __shared__ float sh[32];
    int i = blockIdx.x * blockDim.x + threadIdx.x;
    float s = 0.f;
    if (i < NVERT) {
        float4 dv = g_dv[i];
        float4 a  = g_acc[i];
        float lx = fmaf(a.w, dv.x, -a.x);
        float ly = fmaf(a.w, dv.y, -a.y);
        float lz = fmaf(a.w, dv.z, -a.z);
        s = lx*lx + ly*ly + lz*lz;
    }
    float bs = block_sum(s, sh);
    if (threadIdx.x == 0) atomicAdd(&g_energy[1], (double)bs);
}

__global__ void k_final(float* __restrict__ out) {
    out[0] = (float)(g_energy[0] + CREGU_D * g_energy[1]);
}

// ---------------------------------------------------------------------------
extern "C" void kernel_launch(void* const* d_in, const int* in_sizes, int n_in,
                              void* d_out, int out_size) {
    const float* vertices = (const float*)d_in[0];
    const float* vref     = (const float*)d_in[1];
    const float* quat     = (const float*)d_in[2];
    const float* trans    = (const float*)d_in[3];
    const float* hand     = (const float*)d_in[4];
    const float* intr     = (const float*)d_in[5];
    const float* extr     = (const float*)d_in[6];
    const void*  edges    = d_in[7];
    float* out = (float*)d_out;

    const int TB = 256;
    k_init   <<<1024, TB>>>();
    k_detect <<<1, 256>>>((const int*)edges);
    k_prep   <<<(NVERT + TB - 1) / TB, TB>>>(vertices, vref);
    k_setup  <<<1, 1>>>(quat, trans, intr, extr);
    k_project<<<(NVERT + TB - 1) / TB, TB>>>(vertices);
    k_edges  <<<(NEDGE + TB - 1) / TB, TB>>>(edges);
    k_edata  <<<(IMG_HW / 4 + TB - 1) / TB, TB>>>(hand);
    k_erigid <<<(NVERT + TB - 1) / TB, TB>>>();
    k_final  <<<1, 1>>>(out);
}

// round 5
// speedup vs baseline: 1.3287x; 1.3287x over previous
#include <cuda_runtime.h>

#define NVERT   1000000
#define NEDGE   3000000
#define IMG_W   1024
#define IMG_HW  (1024*1024)
#define MAXD    10.0f
#define CREGU_D 2000.0

// ---- device scratch ----
__device__ float4       g_dv[NVERT];     // vertices - vertices_ref (w = 0)
__device__ float4       g_acc[NVERT];    // xyz = neigh sum, w = deg
__device__ unsigned int g_depth[IMG_HW]; // float bits, atomicMin (all positive)
__device__ double       g_vsum[3];
__device__ double       g_energy[2];     // [0]=e_data, [1]=sum(ldv^2)
__device__ float        g_xf[24];        // M[9], b[3], A[9], c[3]
__device__ int          g_edges64;
__device__ unsigned int g_done;

// ---------------------------------------------------------------------------
__device__ __forceinline__ float block_sum(float v, float* sh) {
    #pragma unroll
    for (int o = 16; o; o >>= 1) v += __shfl_down_sync(0xffffffffu, v, o);
    int lane = threadIdx.x & 31, w = threadIdx.x >> 5;
    __syncthreads();
    if (lane == 0) sh[w] = v;
    __syncthreads();
    int nw = blockDim.x >> 5;
    v = (threadIdx.x < (unsigned)nw) ? sh[threadIdx.x] : 0.0f;
    if (w == 0) {
        #pragma unroll
        for (int o = 16; o; o >>= 1) v += __shfl_down_sync(0xffffffffu, v, o);
    }
    return v;
}

// ---------------------------------------------------------------------------
// init scratch + detect edge dtype (int64 layout => odd 32-bit words all zero)
__global__ void k_init(const int* __restrict__ e) {
    int i = blockIdx.x * blockDim.x + threadIdx.x;
    int stride = gridDim.x * blockDim.x;
    for (int j = i; j < IMG_HW; j += stride) g_depth[j] = 0x41200000u; // 10.0f
    for (int j = i; j < NVERT;  j += stride) g_acc[j] = make_float4(0.f,0.f,0.f,0.f);
    if (blockIdx.x == 0) {
        __shared__ int any;
        if (threadIdx.x == 0) any = 0;
        __syncthreads();
        if (e[2 * threadIdx.x + 1] != 0) atomicOr(&any, 1);
        __syncthreads();
        if (threadIdx.x == 0) {
            g_edges64 = (any == 0) ? 1 : 0;
            g_vsum[0] = g_vsum[1] = g_vsum[2] = 0.0;
            g_energy[0] = g_energy[1] = 0.0;
            g_done = 0u;
        }
    }
}

// per-vertex dv + fp64 mean reduction
__global__ void k_prep(const float* __restrict__ v, const float* __restrict__ vr) {
    __shared__ float sh[32];
    int i = blockIdx.x * blockDim.x + threadIdx.x;
    float sx = 0.f, sy = 0.f, sz = 0.f;
    if (i < NVERT) {
        float x = v[3*i], y = v[3*i+1], z = v[3*i+2];
        g_dv[i] = make_float4(x - vr[3*i], y - vr[3*i+1], z - vr[3*i+2], 0.f);
        sx = x; sy = y; sz = z;
    }
    float bx = block_sum(sx, sh);
    float by = block_sum(sy, sh);
    float bz = block_sum(sz, sh);
    if (threadIdx.x == 0) {
        atomicAdd(&g_vsum[0], (double)bx);
        atomicAdd(&g_vsum[1], (double)by);
        atomicAdd(&g_vsum[2], (double)bz);
    }
}

// fold mean/quat/extrinsic/intrinsic into affine maps; 32 threads prefetch all
// scalar inputs in ONE memory round-trip, thread 0 does the fp64 math.
__global__ void k_setup(const float* __restrict__ q, const float* __restrict__ t,
                        const float* __restrict__ K, const float* __restrict__ E) {
    __shared__ float s_in[32];     // [0..3]=q [4..6]=t [7..15]=K [16..27]=E
    __shared__ double s_vs[3];
    int tid = threadIdx.x;
    if (tid < 4)                    s_in[tid]      = q[tid];
    else if (tid < 7)               s_in[tid]      = t[tid - 4];
    else if (tid < 16)              s_in[tid]      = K[tid - 7];
    else if (tid < 28)              s_in[tid]      = E[tid - 16];
    if (tid < 3)                    s_vs[tid]      = g_vsum[tid];
    __syncthreads();
    if (tid != 0) return;
    const float* Kc = s_in + 7;
    const float* Ec = s_in + 16;
    double inv = 1.0 / (double)NVERT;
    double mx = s_vs[0] * inv, my = s_vs[1] * inv, mz = s_vs[2] * inv;
    double qx = s_in[0], qy = s_in[1], qz = s_in[2], qw = s_in[3];
    double n = 1.0 / sqrt(qx*qx + qy*qy + qz*qz + qw*qw);
    qx *= n; qy *= n; qz *= n; qw *= n;
    double R[9];
    R[0] = 1.0 - 2.0*(qy*qy + qz*qz); R[1] = 2.0*(qx*qy - qw*qz); R[2] = 2.0*(qx*qz + qw*qy);
    R[3] = 2.0*(qx*qy + qw*qz); R[4] = 1.0 - 2.0*(qx*qx + qz*qz); R[5] = 2.0*(qy*qz - qw*qx);
    R[6] = 2.0*(qx*qz - qw*qy); R[7] = 2.0*(qy*qz + qw*qx); R[8] = 1.0 - 2.0*(qx*qx + qy*qy);
    double M[9], b[3];
    for (int r = 0; r < 3; r++) {
        for (int c = 0; c < 3; c++)
            M[r*3+c] = (double)Ec[r*4+0]*R[0*3+c] + (double)Ec[r*4+1]*R[1*3+c] + (double)Ec[r*4+2]*R[2*3+c];
        b[r] = (double)Ec[r*4+0]*s_in[4] + (double)Ec[r*4+1]*s_in[5] + (double)Ec[r*4+2]*s_in[6]
             + (double)Ec[r*4+3] - (M[r*3+0]*mx + M[r*3+1]*my + M[r*3+2]*mz);
    }
    double A[9], c[3];
    for (int r = 0; r < 3; r++) {
        for (int cc = 0; cc < 3; cc++)
            A[r*3+cc] = (double)Kc[r*3+0]*M[0*3+cc] + (double)Kc[r*3+1]*M[1*3+cc] + (double)Kc[r*3+2]*M[2*3+cc];
        c[r] = (double)Kc[r*3+0]*b[0] + (double)Kc[r*3+1]*b[1] + (double)Kc[r*3+2]*b[2];
    }
    for (int j = 0; j < 9; j++) { g_xf[j] = (float)M[j]; g_xf[12+j] = (float)A[j]; }
    for (int j = 0; j < 3; j++) { g_xf[9+j] = (float)b[j]; g_xf[21+j] = (float)c[j]; }
}

// per-vertex projection + z-buffer scatter
__global__ void k_project(const float* __restrict__ v) {
    __shared__ float xf[24];
    if (threadIdx.x < 24) xf[threadIdx.x] = g_xf[threadIdx.x];
    __syncthreads();
    int i = blockIdx.x * blockDim.x + threadIdx.x;
    if (i >= NVERT) return;
    float x = v[3*i], y = v[3*i+1], z = v[3*i+2];
    float pz = fmaf(xf[6], x, fmaf(xf[7], y, fmaf(xf[8], z, xf[11])));
    float px = fmaf(xf[12], x, fmaf(xf[13], y, fmaf(xf[14], z, xf[21])));
    float py = fmaf(xf[15], x, fmaf(xf[16], y, fmaf(xf[17], z, xf[22])));
    float u  = px / pz;
    float vv = py / pz;
    float xi = fminf(fmaxf(rintf(u),  0.0f), (float)(IMG_W - 1));
    float yi = fminf(fmaxf(rintf(vv), 0.0f), (float)(IMG_W - 1));
    int flat = (int)yi * IMG_W + (int)xi;
    float zv = (pz > 0.0f) ? pz : MAXD;
    atomicMin(&g_depth[flat], __float_as_uint(zv));
}

// per-edge scatter via ONE vectorized red per edge:
//   g_acc[src] += {dv[dst].xyz, 1.0}
__global__ void k_edges(const void* __restrict__ ep) {
    int i = blockIdx.x * blockDim.x + threadIdx.x;
    if (i >= NEDGE) return;
    int s, d;
    if (g_edges64) {
        longlong2 p = ((const longlong2*)ep)[i];
        s = (int)p.x; d = (int)p.y;
    } else {
        int2 p = ((const int2*)ep)[i];
        s = p.x; d = p.y;
    }
    float4 dv = __ldg(&g_dv[d]);
    asm volatile("red.global.add.v4.f32 [%0], {%1, %2, %3, %4};"
                 :: "l"(&g_acc[s]), "f"(dv.x), "f"(dv.y), "f"(dv.z), "f"(1.0f)
                 : "memory");
}

// fused tail: e_data (image) + e_rigid (vertices) + final combine
__global__ void k_tail(const float* __restrict__ hand, float* __restrict__ out) {
    __shared__ float sh[32];
    int i = blockIdx.x * blockDim.x + threadIdx.x;

    float s_img = 0.f;
    if (i < IMG_HW / 4) {
        uint4  db = ((const uint4*)g_depth)[i];
        float4 hb = ((const float4*)hand)[i];
        float d0 = __uint_as_float(db.x) - hb.x;
        float d1 = __uint_as_float(db.y) - hb.y;
        float d2 = __uint_as_float(db.z) - hb.z;
        float d3 = __uint_as_float(db.w) - hb.w;
        s_img = d0*d0 + d1*d1 + d2*d2 + d3*d3;
    }
    float s_rig = 0.f;
    if (i < NVERT) {
        float4 dv = g_dv[i];
        float4 a  = g_acc[i];
        float lx = fmaf(a.w, dv.x, -a.x);
        float ly = fmaf(a.w, dv.y, -a.y);
        float lz = fmaf(a.w, dv.z, -a.z);
        s_rig = lx*lx + ly*ly + lz*lz;
    }
    float b0 = block_sum(s_img, sh);
    float b1 = block_sum(s_rig, sh);
    if (threadIdx.x == 0) {
        if (b0 != 0.f) atomicAdd(&g_energy[0], (double)b0);
        if (b1 != 0.f) atomicAdd(&g_energy[1], (double)b1);
        __threadfence();
        unsigned t = atomicAdd(&g_done, 1u);
        if (t == gridDim.x - 1) {
            out[0] = (float)(g_energy[0] + CREGU_D * g_energy[1]);
        }
    }
}

// ---------------------------------------------------------------------------
extern "C" void kernel_launch(void* const* d_in, const int* in_sizes, int n_in,
                              void* d_out, int out_size) {
    const float* vertices = (const float*)d_in[0];
    const float* vref     = (const float*)d_in[1];
    const float* quat     = (const float*)d_in[2];
    const float* trans    = (const float*)d_in[3];
    const float* hand     = (const float*)d_in[4];
    const float* intr     = (const float*)d_in[5];
    const float* extr     = (const float*)d_in[6];
    const void*  edges    = d_in[7];
    float* out = (float*)d_out;

    const int TB = 256;
    int nv_blocks = (NVERT + TB - 1) / TB;           // 3907 (>= IMG_HW/4/TB = 1024)
    k_init   <<<1024, TB>>>((const int*)edges);
    k_prep   <<<nv_blocks, TB>>>(vertices, vref);
    k_setup  <<<1, 32>>>(quat, trans, intr, extr);
    k_project<<<nv_blocks, TB>>>(vertices);
    k_edges  <<<(NEDGE + TB - 1) / TB, TB>>>(edges);
    k_tail   <<<nv_blocks, TB>>>(hand, out);
}

// round 6
// speedup vs baseline: 1.6735x; 1.2595x over previous
#include <cuda_runtime.h>

#define NVERT   1000000
#define NEDGE   3000000
#define IMG_W   1024
#define IMG_HW  (1024*1024)
#define MAXD    10.0f
#define MAXD_BITS 0x41200000u
#define CREGU_D 2000.0

// ---- device scratch ----
__device__ float4       g_dv[NVERT];     // vertices - vertices_ref (w = 0)
__device__ float4       g_acc[NVERT];    // xyz = neigh sum, w = deg
__device__ unsigned int g_depth[IMG_HW]; // float bits, atomicMin (all positive)
__device__ double       g_vsum[3];
__device__ double       g_energy[2];     // [0]=e_data, [1]=sum(ldv^2)
__device__ float        g_xf[24];        // M[9], b[3], A[9], c[3]
__device__ int          g_edges64;
__device__ unsigned int g_done;

// ---------------------------------------------------------------------------
__device__ __forceinline__ float block_sum(float v, float* sh) {
    #pragma unroll
    for (int o = 16; o; o >>= 1) v += __shfl_down_sync(0xffffffffu, v, o);
    int lane = threadIdx.x & 31, w = threadIdx.x >> 5;
    __syncthreads();
    if (lane == 0) sh[w] = v;
    __syncthreads();
    int nw = blockDim.x >> 5;
    v = (threadIdx.x < (unsigned)nw) ? sh[threadIdx.x] : 0.0f;
    if (w == 0) {
        #pragma unroll
        for (int o = 16; o; o >>= 1) v += __shfl_down_sync(0xffffffffu, v, o);
    }
    return v;
}

// ---------------------------------------------------------------------------
// init scratch + detect edge dtype (int64 layout => odd 32-bit words all zero)
__global__ void k_init(const int* __restrict__ e) {
    int i = blockIdx.x * blockDim.x + threadIdx.x;
    int stride = gridDim.x * blockDim.x;
    uint4  dfill = make_uint4(MAXD_BITS, MAXD_BITS, MAXD_BITS, MAXD_BITS);
    float4 zfill = make_float4(0.f, 0.f, 0.f, 0.f);
    uint4* dp = (uint4*)g_depth;
    for (int j = i; j < IMG_HW / 4; j += stride) dp[j] = dfill;
    for (int j = i; j < NVERT;      j += stride) g_acc[j] = zfill;
    if (blockIdx.x == 0) {
        __shared__ int any;
        if (threadIdx.x == 0) any = 0;
        __syncthreads();
        if (e[2 * threadIdx.x + 1] != 0) atomicOr(&any, 1);
        __syncthreads();
        if (threadIdx.x == 0) {
            g_edges64 = (any == 0) ? 1 : 0;
            g_vsum[0] = g_vsum[1] = g_vsum[2] = 0.0;
            g_energy[0] = g_energy[1] = 0.0;
            g_done = 0u;
        }
    }
}

// per-vertex dv + fp64 mean reduction
__global__ void k_prep(const float* __restrict__ v, const float* __restrict__ vr) {
    __shared__ float sh[32];
    int i = blockIdx.x * blockDim.x + threadIdx.x;
    float sx = 0.f, sy = 0.f, sz = 0.f;
    if (i < NVERT) {
        float x = v[3*i], y = v[3*i+1], z = v[3*i+2];
        g_dv[i] = make_float4(x - vr[3*i], y - vr[3*i+1], z - vr[3*i+2], 0.f);
        sx = x; sy = y; sz = z;
    }
    float bx = block_sum(sx, sh);
    float by = block_sum(sy, sh);
    float bz = block_sum(sz, sh);
    if (threadIdx.x == 0) {
        atomicAdd(&g_vsum[0], (double)bx);
        atomicAdd(&g_vsum[1], (double)by);
        atomicAdd(&g_vsum[2], (double)bz);
    }
}

// fold mean/quat/extrinsic/intrinsic into affine maps; 32 threads prefetch all
// scalar inputs in ONE memory round-trip, thread 0 does the fp64 math.
__global__ void k_setup(const float* __restrict__ q, const float* __restrict__ t,
                        const float* __restrict__ K, const float* __restrict__ E) {
    __shared__ float s_in[32];     // [0..3]=q [4..6]=t [7..15]=K [16..27]=E
    __shared__ double s_vs[3];
    int tid = threadIdx.x;
    if (tid < 4)       s_in[tid] = q[tid];
    else if (tid < 7)  s_in[tid] = t[tid - 4];
    else if (tid < 16) s_in[tid] = K[tid - 7];
    else if (tid < 28) s_in[tid] = E[tid - 16];
    if (tid < 3)       s_vs[tid] = g_vsum[tid];
    __syncthreads();
    if (tid != 0) return;
    const float* Kc = s_in + 7;
    const float* Ec = s_in + 16;
    double inv = 1.0 / (double)NVERT;
    double mx = s_vs[0] * inv, my = s_vs[1] * inv, mz = s_vs[2] * inv;
    double qx = s_in[0], qy = s_in[1], qz = s_in[2], qw = s_in[3];
    double n = 1.0 / sqrt(qx*qx + qy*qy + qz*qz + qw*qw);
    qx *= n; qy *= n; qz *= n; qw *= n;
    double R[9];
    R[0] = 1.0 - 2.0*(qy*qy + qz*qz); R[1] = 2.0*(qx*qy - qw*qz); R[2] = 2.0*(qx*qz + qw*qy);
    R[3] = 2.0*(qx*qy + qw*qz); R[4] = 1.0 - 2.0*(qx*qx + qz*qz); R[5] = 2.0*(qy*qz - qw*qx);
    R[6] = 2.0*(qx*qz - qw*qy); R[7] = 2.0*(qy*qz + qw*qx); R[8] = 1.0 - 2.0*(qx*qx + qy*qy);
    double M[9], b[3];
    for (int r = 0; r < 3; r++) {
        for (int c = 0; c < 3; c++)
            M[r*3+c] = (double)Ec[r*4+0]*R[0*3+c] + (double)Ec[r*4+1]*R[1*3+c] + (double)Ec[r*4+2]*R[2*3+c];
        b[r] = (double)Ec[r*4+0]*s_in[4] + (double)Ec[r*4+1]*s_in[5] + (double)Ec[r*4+2]*s_in[6]
             + (double)Ec[r*4+3] - (M[r*3+0]*mx + M[r*3+1]*my + M[r*3+2]*mz);
    }
    double A[9], c[3];
    for (int r = 0; r < 3; r++) {
        for (int cc = 0; cc < 3; cc++)
            A[r*3+cc] = (double)Kc[r*3+0]*M[0*3+cc] + (double)Kc[r*3+1]*M[1*3+cc] + (double)Kc[r*3+2]*M[2*3+cc];
        c[r] = (double)Kc[r*3+0]*b[0] + (double)Kc[r*3+1]*b[1] + (double)Kc[r*3+2]*b[2];
    }
    for (int j = 0; j < 9; j++) { g_xf[j] = (float)M[j]; g_xf[12+j] = (float)A[j]; }
    for (int j = 0; j < 3; j++) { g_xf[9+j] = (float)b[j]; g_xf[21+j] = (float)c[j]; }
}

// per-vertex projection + z-buffer scatter.
// Corner pixels (the clamp hot-spots: up to ~24K same-address atomics) are
// privatized into 4 shared-memory min slots, flushed once per block.
__global__ void k_project(const float* __restrict__ v) {
    __shared__ float xf[24];
    __shared__ unsigned cmin[4];
    if (threadIdx.x < 24) xf[threadIdx.x] = g_xf[threadIdx.x];
    if (threadIdx.x < 4)  cmin[threadIdx.x] = MAXD_BITS;
    __syncthreads();
    int i = blockIdx.x * blockDim.x + threadIdx.x;
    if (i < NVERT) {
        float x = v[3*i], y = v[3*i+1], z = v[3*i+2];
        float pz = fmaf(xf[6], x, fmaf(xf[7], y, fmaf(xf[8], z, xf[11])));
        float px = fmaf(xf[12], x, fmaf(xf[13], y, fmaf(xf[14], z, xf[21])));
        float py = fmaf(xf[15], x, fmaf(xf[16], y, fmaf(xf[17], z, xf[22])));
        float u  = px / pz;
        float vv = py / pz;
        int xi = (int)fminf(fmaxf(rintf(u),  0.0f), (float)(IMG_W - 1));
        int yi = (int)fminf(fmaxf(rintf(vv), 0.0f), (float)(IMG_W - 1));
        float zv = (pz > 0.0f) ? pz : MAXD;
        unsigned bits = __float_as_uint(zv);
        bool xe = (xi == 0) | (xi == IMG_W - 1);
        bool ye = (yi == 0) | (yi == IMG_W - 1);
        if (xe & ye) {
            int cidx = ((yi != 0) ? 2 : 0) | ((xi != 0) ? 1 : 0);
            atomicMin(&cmin[cidx], bits);
        } else {
            atomicMin(&g_depth[yi * IMG_W + xi], bits);
        }
    }
    __syncthreads();
    if (threadIdx.x < 4) {
        unsigned m = cmin[threadIdx.x];
        if (m != MAXD_BITS) {
            int flat = ((threadIdx.x & 2) ? (IMG_W - 1) * IMG_W : 0)
                     + ((threadIdx.x & 1) ? (IMG_W - 1) : 0);
            atomicMin(&g_depth[flat], m);
        }
    }
}

// per-edge scatter via ONE vectorized red per edge: g_acc[src] += {dv[dst].xyz, 1}
__global__ void k_edges(const void* __restrict__ ep) {
    int i = blockIdx.x * blockDim.x + threadIdx.x;
    if (i >= NEDGE) return;
    int s, d;
    if (g_edges64) {
        longlong2 p = ((const longlong2*)ep)[i];
        s = (int)p.x; d = (int)p.y;
    } else {
        int2 p = ((const int2*)ep)[i];
        s = p.x; d = p.y;
    }
    float4 dv = __ldg(&g_dv[d]);
    asm volatile("red.global.add.v4.f32 [%0], {%1, %2, %3, %4};"
                 :: "l"(&g_acc[s]), "f"(dv.x), "f"(dv.y), "f"(dv.z), "f"(1.0f)
                 : "memory");
}

// fused tail: e_data (image) + e_rigid (vertices) + final combine
__global__ void k_tail(const float* __restrict__ hand, float* __restrict__ out) {
    __shared__ float sh[32];
    int i = blockIdx.x * blockDim.x + threadIdx.x;

    float s_img = 0.f;
    if (i < IMG_HW / 4) {
        uint4  db = ((const uint4*)g_depth)[i];
        float4 hb = ((const float4*)hand)[i];
        float d0 = __uint_as_float(db.x) - hb.x;
        float d1 = __uint_as_float(db.y) - hb.y;
        float d2 = __uint_as_float(db.z) - hb.z;
        float d3 = __uint_as_float(db.w) - hb.w;
        s_img = d0*d0 + d1*d1 + d2*d2 + d3*d3;
    }
    float s_rig = 0.f;
    if (i < NVERT) {
        float4 dv = g_dv[i];
        float4 a  = g_acc[i];
        float lx = fmaf(a.w, dv.x, -a.x);
        float ly = fmaf(a.w, dv.y, -a.y);
        float lz = fmaf(a.w, dv.z, -a.z);
        s_rig = lx*lx + ly*ly + lz*lz;
    }
    float b0 = block_sum(s_img, sh);
    float b1 = block_sum(s_rig, sh);
    if (threadIdx.x == 0) {
        if (b0 != 0.f) atomicAdd(&g_energy[0], (double)b0);
        if (b1 != 0.f) atomicAdd(&g_energy[1], (double)b1);
        __threadfence();
        unsigned t = atomicAdd(&g_done, 1u);
        if (t == gridDim.x - 1) {
            out[0] = (float)(g_energy[0] + CREGU_D * g_energy[1]);
        }
    }
}

// ---------------------------------------------------------------------------
extern "C" void kernel_launch(void* const* d_in, const int* in_sizes, int n_in,
                              void* d_out, int out_size) {
    const float* vertices = (const float*)d_in[0];
    const float* vref     = (const float*)d_in[1];
    const float* quat     = (const float*)d_in[2];
    const float* trans    = (const float*)d_in[3];
    const float* hand     = (const float*)d_in[4];
    const float* intr     = (const float*)d_in[5];
    const float* extr     = (const float*)d_in[6];
    const void*  edges    = d_in[7];
    float* out = (float*)d_out;

    const int TB = 256;
    int nv_blocks = (NVERT + TB - 1) / TB;
    k_init   <<<1024, TB>>>((const int*)edges);
    k_prep   <<<nv_blocks, TB>>>(vertices, vref);
    k_setup  <<<1, 32>>>(quat, trans, intr, extr);
    k_project<<<nv_blocks, TB>>>(vertices);
    k_edges  <<<(NEDGE + TB - 1) / TB, TB>>>(edges);
    k_tail   <<<nv_blocks, TB>>>(hand, out);
}

// round 7
// speedup vs baseline: 1.7056x; 1.0192x over previous
#include <cuda_runtime.h>

#define NVERT   1000000
#define NEDGE   3000000
#define IMG_W   1024
#define IMG_HW  (1024*1024)
#define MAXD    10.0f
#define MAXD_BITS 0x41200000u
#define CREGU_D 2000.0

// ---- device scratch ----
__device__ float4       g_dv[NVERT];     // vertices - vertices_ref (w = 0)
__device__ float4       g_acc[NVERT];    // xyz = neigh sum, w = deg
__device__ unsigned int g_depth[IMG_HW]; // float bits, atomicMin (all positive)
__device__ double       g_vsum[3];
__device__ double       g_energy[2];     // [0]=e_data, [1]=sum(ldv^2)
__device__ float        g_xf[24];        // M[9], b[3], A[9], c[3]
__device__ int          g_edges64;
__device__ unsigned int g_done;

// ---------------------------------------------------------------------------
__device__ __forceinline__ float block_sum(float v, float* sh) {
    #pragma unroll
    for (int o = 16; o; o >>= 1) v += __shfl_down_sync(0xffffffffu, v, o);
    int lane = threadIdx.x & 31, w = threadIdx.x >> 5;
    __syncthreads();
    if (lane == 0) sh[w] = v;
    __syncthreads();
    int nw = blockDim.x >> 5;
    v = (threadIdx.x < (unsigned)nw) ? sh[threadIdx.x] : 0.0f;
    if (w == 0) {
        #pragma unroll
        for (int o = 16; o; o >>= 1) v += __shfl_down_sync(0xffffffffu, v, o);
    }
    return v;
}

// ---------------------------------------------------------------------------
// fused: depth fill + acc zero + dv compute + fp64 mean reduction
__global__ void k_prep(const float* __restrict__ v, const float* __restrict__ vr) {
    __shared__ float sh[32];
    int i = blockIdx.x * blockDim.x + threadIdx.x;

    // depth fill: 262144 uint4 stores, first 262144 threads take one each
    if (i < IMG_HW / 4)
        ((uint4*)g_depth)[i] = make_uint4(MAXD_BITS, MAXD_BITS, MAXD_BITS, MAXD_BITS);

    float sx = 0.f, sy = 0.f, sz = 0.f;
    if (i < NVERT) {
        float x = v[3*i], y = v[3*i+1], z = v[3*i+2];
        g_dv[i]  = make_float4(x - vr[3*i], y - vr[3*i+1], z - vr[3*i+2], 0.f);
        g_acc[i] = make_float4(0.f, 0.f, 0.f, 0.f);
        sx = x; sy = y; sz = z;
    }
    float bx = block_sum(sx, sh);
    float by = block_sum(sy, sh);
    float bz = block_sum(sz, sh);
    if (threadIdx.x == 0) {
        atomicAdd(&g_vsum[0], (double)bx);
        atomicAdd(&g_vsum[1], (double)by);
        atomicAdd(&g_vsum[2], (double)bz);
    }
}

// fold mean/quat/extrinsic/intrinsic into affine maps; also: edge dtype
// detection (int64 layout => odd 32-bit words all zero) + flag/energy reset.
// 256 threads prefetch everything in one round-trip; thread 0 does fp64 math.
__global__ void k_setup(const float* __restrict__ q, const float* __restrict__ t,
                        const float* __restrict__ K, const float* __restrict__ E,
                        const int* __restrict__ e) {
    __shared__ float s_in[32];     // [0..3]=q [4..6]=t [7..15]=K [16..27]=E
    __shared__ double s_vs[3];
    __shared__ int any;
    int tid = threadIdx.x;
    if (tid == 0) any = 0;
    if (tid < 4)       s_in[tid] = q[tid];
    else if (tid < 7)  s_in[tid] = t[tid - 4];
    else if (tid < 16) s_in[tid] = K[tid - 7];
    else if (tid < 28) s_in[tid] = E[tid - 16];
    if (tid < 3)       s_vs[tid] = g_vsum[tid];
    __syncthreads();
    if (e[2 * tid + 1] != 0) atomicOr(&any, 1);
    __syncthreads();
    if (tid != 0) return;
    g_edges64 = (any == 0) ? 1 : 0;
    g_energy[0] = g_energy[1] = 0.0;
    g_done = 0u;
    // reset vsum for next graph replay (we already captured it in s_vs)
    g_vsum[0] = g_vsum[1] = g_vsum[2] = 0.0;

    const float* Kc = s_in + 7;
    const float* Ec = s_in + 16;
    double inv = 1.0 / (double)NVERT;
    double mx = s_vs[0] * inv, my = s_vs[1] * inv, mz = s_vs[2] * inv;
    double qx = s_in[0], qy = s_in[1], qz = s_in[2], qw = s_in[3];
    double n = 1.0 / sqrt(qx*qx + qy*qy + qz*qz + qw*qw);
    qx *= n; qy *= n; qz *= n; qw *= n;
    double R[9];
    R[0] = 1.0 - 2.0*(qy*qy + qz*qz); R[1] = 2.0*(qx*qy - qw*qz); R[2] = 2.0*(qx*qz + qw*qy);
    R[3] = 2.0*(qx*qy + qw*qz); R[4] = 1.0 - 2.0*(qx*qx + qz*qz); R[5] = 2.0*(qy*qz - qw*qx);
    R[6] = 2.0*(qx*qz - qw*qy); R[7] = 2.0*(qy*qz + qw*qx); R[8] = 1.0 - 2.0*(qx*qx + qy*qy);
    double M[9], b[3];
    for (int r = 0; r < 3; r++) {
        for (int c = 0; c < 3; c++)
            M[r*3+c] = (double)Ec[r*4+0]*R[0*3+c] + (double)Ec[r*4+1]*R[1*3+c] + (double)Ec[r*4+2]*R[2*3+c];
        b[r] = (double)Ec[r*4+0]*s_in[4] + (double)Ec[r*4+1]*s_in[5] + (double)Ec[r*4+2]*s_in[6]
             + (double)Ec[r*4+3] - (M[r*3+0]*mx + M[r*3+1]*my + M[r*3+2]*mz);
    }
    double A[9], c[3];
    for (int r = 0; r < 3; r++) {
        for (int cc = 0; cc < 3; cc++)
            A[r*3+cc] = (double)Kc[r*3+0]*M[0*3+cc] + (double)Kc[r*3+1]*M[1*3+cc] + (double)Kc[r*3+2]*M[2*3+cc];
        c[r] = (double)Kc[r*3+0]*b[0] + (double)Kc[r*3+1]*b[1] + (double)Kc[r*3+2]*b[2];
    }
    for (int j = 0; j < 9; j++) { g_xf[j] = (float)M[j]; g_xf[12+j] = (float)A[j]; }
    for (int j = 0; j < 3; j++) { g_xf[9+j] = (float)b[j]; g_xf[21+j] = (float)c[j]; }
}

// per-vertex projection + z-buffer scatter; single reciprocal, corner
// pixels privatized into shared-memory min slots (clamp hot-spots).
__global__ void k_project(const float* __restrict__ v) {
    __shared__ float xf[24];
    __shared__ unsigned cmin[4];
    if (threadIdx.x < 24) xf[threadIdx.x] = g_xf[threadIdx.x];
    if (threadIdx.x < 4)  cmin[threadIdx.x] = MAXD_BITS;
    __syncthreads();
    int i = blockIdx.x * blockDim.x + threadIdx.x;
    if (i < NVERT) {
        float x = v[3*i], y = v[3*i+1], z = v[3*i+2];
        float pz = fmaf(xf[6], x, fmaf(xf[7], y, fmaf(xf[8], z, xf[11])));
        float px = fmaf(xf[12], x, fmaf(xf[13], y, fmaf(xf[14], z, xf[21])));
        float py = fmaf(xf[15], x, fmaf(xf[16], y, fmaf(xf[17], z, xf[22])));
        float rpz = 1.0f / pz;                       // one div instead of two
        int xi = (int)fminf(fmaxf(rintf(px * rpz), 0.0f), (float)(IMG_W - 1));
        int yi = (int)fminf(fmaxf(rintf(py * rpz), 0.0f), (float)(IMG_W - 1));
        float zv = (pz > 0.0f) ? pz : MAXD;
        unsigned bits = __float_as_uint(zv);
        bool xe = (xi == 0) | (xi == IMG_W - 1);
        bool ye = (yi == 0) | (yi == IMG_W - 1);
        if (xe & ye) {
            int cidx = ((yi != 0) ? 2 : 0) | ((xi != 0) ? 1 : 0);
            atomicMin(&cmin[cidx], bits);
        } else {
            atomicMin(&g_depth[yi * IMG_W + xi], bits);
        }
    }
    __syncthreads();
    if (threadIdx.x < 4) {
        unsigned m = cmin[threadIdx.x];
        if (m != MAXD_BITS) {
            int flat = ((threadIdx.x & 2) ? (IMG_W - 1) * IMG_W : 0)
                     + ((threadIdx.x & 1) ? (IMG_W - 1) : 0);
            atomicMin(&g_depth[flat], m);
        }
    }
}

// per-edge scatter, 2 edges/thread; one vectorized red per edge:
//   g_acc[src] += {dv[dst].xyz, 1}
__device__ __forceinline__ void edge_red(int s, int d) {
    float4 dv = __ldg(&g_dv[d]);
    asm volatile("red.global.add.v4.f32 [%0], {%1, %2, %3, %4};"
                 :: "l"(&g_acc[s]), "f"(dv.x), "f"(dv.y), "f"(dv.z), "f"(1.0f)
                 : "memory");
}

__global__ void k_edges(const void* __restrict__ ep) {
    int i = blockIdx.x * blockDim.x + threadIdx.x;   // edge-pair index
    if (i >= NEDGE / 2) return;
    if (g_edges64) {
        longlong2 p0 = ((const longlong2*)ep)[2*i];
        longlong2 p1 = ((const longlong2*)ep)[2*i + 1];
        edge_red((int)p0.x, (int)p0.y);
        edge_red((int)p1.x, (int)p1.y);
    } else {
        int4 p = ((const int4*)ep)[i];               // two int32 edges
        edge_red(p.x, p.y);
        edge_red(p.z, p.w);
    }
}

// fused tail: e_data (image) + e_rigid (vertices) + final combine
__global__ void k_tail(const float* __restrict__ hand, float* __restrict__ out) {
    __shared__ float sh[32];
    int i = blockIdx.x * blockDim.x + threadIdx.x;

    float s_img = 0.f;
    if (i < IMG_HW / 4) {
        uint4  db = ((const uint4*)g_depth)[i];
        float4 hb = ((const float4*)hand)[i];
        float d0 = __uint_as_float(db.x) - hb.x;
        float d1 = __uint_as_float(db.y) - hb.y;
        float d2 = __uint_as_float(db.z) - hb.z;
        float d3 = __uint_as_float(db.w) - hb.w;
        s_img = d0*d0 + d1*d1 + d2*d2 + d3*d3;
    }
    float s_rig = 0.f;
    if (i < NVERT) {
        float4 dv = g_dv[i];
        float4 a  = g_acc[i];
        float lx = fmaf(a.w, dv.x, -a.x);
        float ly = fmaf(a.w, dv.y, -a.y);
        float lz = fmaf(a.w, dv.z, -a.z);
        s_rig = lx*lx + ly*ly + lz*lz;
    }
    float b0 = block_sum(s_img, sh);
    float b1 = block_sum(s_rig, sh);
    if (threadIdx.x == 0) {
        if (b0 != 0.f) atomicAdd(&g_energy[0], (double)b0);
        if (b1 != 0.f) atomicAdd(&g_energy[1], (double)b1);
        __threadfence();
        unsigned t = atomicAdd(&g_done, 1u);
        if (t == gridDim.x - 1) {
            out[0] = (float)(g_energy[0] + CREGU_D * g_energy[1]);
        }
    }
}

// ---------------------------------------------------------------------------
extern "C" void kernel_launch(void* const* d_in, const int* in_sizes, int n_in,
                              void* d_out, int out_size) {
    const float* vertices = (const float*)d_in[0];
    const float* vref     = (const float*)d_in[1];
    const float* quat     = (const float*)d_in[2];
    const float* trans    = (const float*)d_in[3];
    const float* hand     = (const float*)d_in[4];
    const float* intr     = (const float*)d_in[5];
    const float* extr     = (const float*)d_in[6];
    const void*  edges    = d_in[7];
    float* out = (float*)d_out;

    const int TB = 256;
    int nv_blocks = (NVERT + TB - 1) / TB;
    k_prep   <<<nv_blocks, TB>>>(vertices, vref);
    k_setup  <<<1, 256>>>(quat, trans, intr, extr, (const int*)edges);
    k_project<<<nv_blocks, TB>>>(vertices);
    k_edges  <<<(NEDGE / 2 + TB - 1) / TB, TB>>>(edges);
    k_tail   <<<nv_blocks, TB>>>(hand, out);
}